// round 12
// baseline (speedup 1.0000x reference)
#include <cuda_runtime.h>
#include <cuda_bf16.h>
#include <cstdint>
#include <math.h>

// Problem constants
#define D_MODEL  1024
#define D_INNER  2048
#define D_STATE  16
#define D_CONV   4
#define DT_RANK  64
#define BATCH    2
#define SEQ      1024
#define ROWS     (BATCH*SEQ)           // 2048
#define XDBL_W   (DT_RANK + 2*D_STATE) // 96

// ---------------------------------------------------------------------------
// Scratch (static device arrays; no allocation allowed)
// ---------------------------------------------------------------------------
__device__ float g_xz  [ROWS * 2 * D_INNER];    // [xi | z]
__device__ float g_u   [ROWS * D_INNER];
__device__ float g_xdbl[ROWS * XDBL_W];         // [dt_r | B | C] (B,C used by scan)
__device__ float g_dt  [ROWS * D_INNER];

// bf16 split operands for tensor-core GEMMs
__device__ __nv_bfloat16 g_hhi [ROWS * D_MODEL];
__device__ __nv_bfloat16 g_hlo [ROWS * D_MODEL];
__device__ __nv_bfloat16 g_wint_hi[(2*D_INNER) * D_MODEL]; // W_in^T  [4096,1024]
__device__ __nv_bfloat16 g_wint_lo[(2*D_INNER) * D_MODEL];
__device__ __nv_bfloat16 g_yhi [ROWS * D_INNER];
__device__ __nv_bfloat16 g_ylo [ROWS * D_INNER];
__device__ __nv_bfloat16 g_wot_hi[D_MODEL * D_INNER];      // W_out^T [1024,2048]
__device__ __nv_bfloat16 g_wot_lo[D_MODEL * D_INNER];
__device__ __nv_bfloat16 g_dtr_hi[ROWS * DT_RANK];         // dt_r split [2048,64]
__device__ __nv_bfloat16 g_dtr_lo[ROWS * DT_RANK];
__device__ __nv_bfloat16 g_wdtt_hi[D_INNER * DT_RANK];     // W_dt^T [2048,64]
__device__ __nv_bfloat16 g_wdtt_lo[D_INNER * DT_RANK];

// ---------------------------------------------------------------------------
// PTX helpers (sm_80-era only: ldmatrix / mma.sync / cp.async)
// ---------------------------------------------------------------------------
__device__ __forceinline__ uint32_t smem_to_u32(const void* p) {
    uint32_t a;
    asm("{ .reg .u64 t; cvta.to.shared.u64 t, %1; cvt.u32.u64 %0, t; }" : "=r"(a) : "l"(p));
    return a;
}
#define CP_ASYNC_16(dst_u32, src_ptr) \
    asm volatile("cp.async.cg.shared.global [%0], [%1], 16;" :: "r"(dst_u32), "l"(src_ptr))
#define CP_COMMIT() asm volatile("cp.async.commit_group;" ::: "memory")
#define CP_WAIT(n)  asm volatile("cp.async.wait_group %0;" :: "n"(n) : "memory")

#define LDSM_X4(r0,r1,r2,r3,addr) \
    asm volatile("ldmatrix.sync.aligned.m8n8.x4.shared.b16 {%0,%1,%2,%3}, [%4];" \
        : "=r"(r0),"=r"(r1),"=r"(r2),"=r"(r3) : "r"(addr))

__device__ __forceinline__ void mma_bf16(float* c, const uint32_t* a, const uint32_t* b) {
    asm volatile(
        "mma.sync.aligned.m16n8k16.row.col.f32.bf16.bf16.f32 "
        "{%0,%1,%2,%3}, {%4,%5,%6,%7}, {%8,%9}, {%0,%1,%2,%3};"
        : "+f"(c[0]), "+f"(c[1]), "+f"(c[2]), "+f"(c[3])
        : "r"(a[0]), "r"(a[1]), "r"(a[2]), "r"(a[3]), "r"(b[0]), "r"(b[1]));
}

// ---------------------------------------------------------------------------
// Math helpers
// ---------------------------------------------------------------------------
__device__ __forceinline__ float sigmoidf_(float x) { return 1.0f / (1.0f + __expf(-x)); }
__device__ __forceinline__ float softplusf_(float x) {
    return fmaxf(x, 0.0f) + log1pf(__expf(-fabsf(x)));
}
__device__ __forceinline__ void split_bf16(float v, __nv_bfloat16& hi, __nv_bfloat16& lo) {
    hi = __float2bfloat16(v);
    lo = __float2bfloat16(v - __bfloat162float(hi));
}

// ---------------------------------------------------------------------------
// K1: LayerNorm -> bf16-split (g_hhi / g_hlo)
// ---------------------------------------------------------------------------
__global__ void ln_kernel(const float* __restrict__ x,
                          const float* __restrict__ gamma,
                          const float* __restrict__ beta) {
    const int row = blockIdx.x;
    const int tid = threadIdx.x;
    const float4* xv = reinterpret_cast<const float4*>(x + (size_t)row * D_MODEL);
    float4 v = xv[tid];
    float s  = v.x + v.y + v.z + v.w;
    float s2 = v.x*v.x + v.y*v.y + v.z*v.z + v.w*v.w;

    #pragma unroll
    for (int o = 16; o > 0; o >>= 1) {
        s  += __shfl_xor_sync(0xffffffffu, s,  o);
        s2 += __shfl_xor_sync(0xffffffffu, s2, o);
    }
    __shared__ float red0[8], red1[8];
    const int wid = tid >> 5, lane = tid & 31;
    if (lane == 0) { red0[wid] = s; red1[wid] = s2; }
    __syncthreads();
    if (wid == 0) {
        s  = (lane < 8) ? red0[lane] : 0.f;
        s2 = (lane < 8) ? red1[lane] : 0.f;
        #pragma unroll
        for (int o = 4; o > 0; o >>= 1) {
            s  += __shfl_xor_sync(0xffffffffu, s,  o);
            s2 += __shfl_xor_sync(0xffffffffu, s2, o);
        }
        if (lane == 0) { red0[0] = s; red1[0] = s2; }
    }
    __syncthreads();
    const float mean = red0[0] * (1.0f / D_MODEL);
    const float var  = red1[0] * (1.0f / D_MODEL) - mean * mean;
    const float rstd = rsqrtf(var + 1e-5f);

    const float4 g  = reinterpret_cast<const float4*>(gamma)[tid];
    const float4 be = reinterpret_cast<const float4*>(beta)[tid];
    float o[4];
    o[0] = (v.x - mean) * rstd * g.x + be.x;
    o[1] = (v.y - mean) * rstd * g.y + be.y;
    o[2] = (v.z - mean) * rstd * g.z + be.z;
    o[3] = (v.w - mean) * rstd * g.w + be.w;
    const size_t base = (size_t)row * D_MODEL + tid * 4;
    #pragma unroll
    for (int j = 0; j < 4; j++) {
        __nv_bfloat16 hi, lo;
        split_bf16(o[j], hi, lo);
        g_hhi[base + j] = hi;
        g_hlo[base + j] = lo;
    }
}

// ---------------------------------------------------------------------------
// K2: tiled transpose + bf16-split: in[R,C] fp32 -> out[C,R] (hi,lo)
// ---------------------------------------------------------------------------
__global__ void transpose_split_kernel(const float* __restrict__ in, int R, int C,
                                       __nv_bfloat16* __restrict__ outhi,
                                       __nv_bfloat16* __restrict__ outlo) {
    __shared__ float tile[32][33];
    const int c0 = blockIdx.x * 32;
    const int r0 = blockIdx.y * 32;
    const int tx = threadIdx.x, ty = threadIdx.y;   // 32 x 8
    #pragma unroll
    for (int i = 0; i < 32; i += 8)
        tile[ty + i][tx] = in[(size_t)(r0 + ty + i) * C + c0 + tx];
    __syncthreads();
    #pragma unroll
    for (int i = 0; i < 32; i += 8) {
        float v = tile[tx][ty + i];
        __nv_bfloat16 hi, lo;
        split_bf16(v, hi, lo);
        size_t oidx = (size_t)(c0 + ty + i) * R + r0 + tx;
        outhi[oidx] = hi;
        outlo[oidx] = lo;
    }
}

// ---------------------------------------------------------------------------
// K3: bf16-split GEMM via mma.sync — 4-stage cp.async ring, prefetch dist 3.
//   C[M,N] = op(Ahi@B^T(3-term) [+bias][softplus]) [+ Cadd]
// ---------------------------------------------------------------------------
#define GT_ROWB    80
#define GT_STAGES  4

template<int BMROWS>
__device__ __forceinline__ void tile_cp_async(uint32_t smem_tile,
                                              const __nv_bfloat16* __restrict__ src,
                                              int ldk, int tid) {
    #pragma unroll
    for (int i = tid; i < BMROWS * 4; i += 256) {
        const int row   = i >> 2;
        const int chunk = i & 3;
        const __nv_bfloat16* g = src + (size_t)row * ldk + chunk * 8;
        CP_ASYNC_16(smem_tile + row * GT_ROWB + chunk * 16, g);
    }
}

template<int BM, bool SOFTPLUS>
__global__ void __launch_bounds__(256)
bf16split_gemm(const __nv_bfloat16* __restrict__ Ahi, const __nv_bfloat16* __restrict__ Alo,
               const __nv_bfloat16* __restrict__ Bhi, const __nv_bfloat16* __restrict__ Blo,
               float* __restrict__ C, const float* __restrict__ Cadd,
               const float* __restrict__ bias,
               int M, int N, int K) {
    constexpr int MI      = BM / 32;                 // m-fragments per warp
    constexpr int A_TILE  = BM * GT_ROWB;
    constexpr int B_TILE  = 128 * GT_ROWB;
    constexpr int ST_AHI  = 0;
    constexpr int ST_ALO  = ST_AHI + A_TILE;
    constexpr int ST_BHI  = ST_ALO + A_TILE;
    constexpr int ST_BLO  = ST_BHI + B_TILE;
    constexpr int STAGE   = 2 * A_TILE + 2 * B_TILE;

    extern __shared__ char smem[];
    const uint32_t sbase = smem_to_u32(smem);
    const int tid = threadIdx.x;
    const int wid = tid >> 5, L = tid & 31;
    const int wm = wid & 1;
    const int wn = wid >> 1;
    const int m0 = blockIdx.y * BM;
    const int n0 = blockIdx.x * 128;

    const uint32_t a_lane = (uint32_t)((wm * (BM / 2) + (L & 15)) * GT_ROWB + (L >> 4) * 16);
    const uint32_t b_lane = (uint32_t)((wn * 32 + (L & 7) + ((L >> 4) << 3)) * GT_ROWB
                                       + ((L >> 3) & 1) * 16);

    float acc[MI][4][4];
    #pragma unroll
    for (int i = 0; i < MI; i++)
        #pragma unroll
        for (int j = 0; j < 4; j++)
            #pragma unroll
            for (int k = 0; k < 4; k++) acc[i][j][k] = 0.f;

    const int NC = K >> 5;
    const size_t abase = (size_t)m0 * K;
    const size_t bbase = (size_t)n0 * K;

    // prologue: issue chunks 0..2 (one commit group each; empty groups OK)
    #pragma unroll
    for (int s = 0; s < GT_STAGES - 1; s++) {
        if (s < NC) {
            const uint32_t st = sbase + s * STAGE;
            const int kc = s << 5;
            tile_cp_async<BM >(st + ST_AHI, Ahi + abase + kc, K, tid);
            tile_cp_async<BM >(st + ST_ALO, Alo + abase + kc, K, tid);
            tile_cp_async<128>(st + ST_BHI, Bhi + bbase + kc, K, tid);
            tile_cp_async<128>(st + ST_BLO, Blo + bbase + kc, K, tid);
        }
        CP_COMMIT();
    }

    for (int c = 0; c < NC; c++) {
        const uint32_t stage = sbase + (c & 3) * STAGE;

        // issue chunk c+3 (or empty commit to keep group accounting uniform)
        {
            const int p = c + GT_STAGES - 1;
            if (p < NC) {
                const uint32_t st = sbase + (p & 3) * STAGE;
                const int kc = p << 5;
                tile_cp_async<BM >(st + ST_AHI, Ahi + abase + kc, K, tid);
                tile_cp_async<BM >(st + ST_ALO, Alo + abase + kc, K, tid);
                tile_cp_async<128>(st + ST_BHI, Bhi + bbase + kc, K, tid);
                tile_cp_async<128>(st + ST_BLO, Blo + bbase + kc, K, tid);
            }
            CP_COMMIT();
        }
        CP_WAIT(GT_STAGES - 1);   // chunk c's group complete
        __syncthreads();

        const uint32_t sAhi = stage + ST_AHI + a_lane;
        const uint32_t sAlo = stage + ST_ALO + a_lane;
        const uint32_t sBhi = stage + ST_BHI + b_lane;
        const uint32_t sBlo = stage + ST_BLO + b_lane;

        #pragma unroll
        for (int ks = 0; ks < 2; ks++) {
            uint32_t bh[8], bl[8];
            LDSM_X4(bh[0], bh[1], bh[2], bh[3], sBhi + 0 * 16 * GT_ROWB + ks * 32);
            LDSM_X4(bh[4], bh[5], bh[6], bh[7], sBhi + 1 * 16 * GT_ROWB + ks * 32);
            LDSM_X4(bl[0], bl[1], bl[2], bl[3], sBlo + 0 * 16 * GT_ROWB + ks * 32);
            LDSM_X4(bl[4], bl[5], bl[6], bl[7], sBlo + 1 * 16 * GT_ROWB + ks * 32);
            #pragma unroll
            for (int mi = 0; mi < MI; mi++) {
                uint32_t ah[4], al[4];
                LDSM_X4(ah[0], ah[1], ah[2], ah[3], sAhi + mi * 16 * GT_ROWB + ks * 32);
                LDSM_X4(al[0], al[1], al[2], al[3], sAlo + mi * 16 * GT_ROWB + ks * 32);
                #pragma unroll
                for (int ni = 0; ni < 4; ni++) {
                    mma_bf16(acc[mi][ni], ah, &bh[ni * 2]);
                    mma_bf16(acc[mi][ni], ah, &bl[ni * 2]);
                    mma_bf16(acc[mi][ni], al, &bh[ni * 2]);
                }
            }
        }
        __syncthreads();   // protect stage (c&3) from overwrite at iter c+1
    }

    const int g  = L >> 2;
    const int tg = L & 3;
    #pragma unroll
    for (int mi = 0; mi < MI; mi++) {
        const int r0 = m0 + wm * (BM / 2) + mi * 16 + g;
        #pragma unroll
        for (int ni = 0; ni < 4; ni++) {
            const int cc = n0 + wn * 32 + ni * 8 + tg * 2;
            float2 v0 = make_float2(acc[mi][ni][0], acc[mi][ni][1]);
            float2 v1 = make_float2(acc[mi][ni][2], acc[mi][ni][3]);
            if (bias) {
                const float2 bv = *reinterpret_cast<const float2*>(bias + cc);
                v0.x += bv.x; v0.y += bv.y;
                v1.x += bv.x; v1.y += bv.y;
            }
            if (SOFTPLUS) {
                v0.x = softplusf_(v0.x); v0.y = softplusf_(v0.y);
                v1.x = softplusf_(v1.x); v1.y = softplusf_(v1.y);
            }
            if (Cadd) {
                const float2 a0 = *reinterpret_cast<const float2*>(Cadd + (size_t)r0 * N + cc);
                const float2 a1 = *reinterpret_cast<const float2*>(Cadd + (size_t)(r0 + 8) * N + cc);
                v0.x += a0.x; v0.y += a0.y;
                v1.x += a1.x; v1.y += a1.y;
            }
            *reinterpret_cast<float2*>(C + (size_t)r0 * N + cc)       = v0;
            *reinterpret_cast<float2*>(C + (size_t)(r0 + 8) * N + cc) = v1;
        }
    }
}

#define GT_SMEM_128  (GT_STAGES * (2 * 128 * GT_ROWB + 2 * 128 * GT_ROWB))   // 163840

// ---------------------------------------------------------------------------
// K4: depthwise causal conv + bias + silu — float4 lanes (4 d per thread).
// ---------------------------------------------------------------------------
#define CONV_TSEG 64
__global__ void __launch_bounds__(128) conv_silu_kernel(const float* __restrict__ Wc,
                                                        const float* __restrict__ bc) {
    const int d4 = (blockIdx.x * 128 + threadIdx.x) * 4;   // 4 consecutive d
    const int t0 = blockIdx.y * CONV_TSEG;
    const int b  = blockIdx.z;
    const int rowbase = b * SEQ + t0;

    // per-lane taps: Wc rows d4..d4+3 (4 floats each) = 4 float4 loads
    float4 W[4];
    #pragma unroll
    for (int j = 0; j < 4; j++)
        W[j] = *reinterpret_cast<const float4*>(Wc + (size_t)(d4 + j) * D_CONV);
    const float4 bias = *reinterpret_cast<const float4*>(bc + d4);

    float4 xm3 = (t0 >= 3) ? *reinterpret_cast<const float4*>(g_xz + (size_t)(rowbase - 3) * (2 * D_INNER) + d4)
                           : make_float4(0.f, 0.f, 0.f, 0.f);
    float4 xm2 = (t0 >= 2) ? *reinterpret_cast<const float4*>(g_xz + (size_t)(rowbase - 2) * (2 * D_INNER) + d4)
                           : make_float4(0.f, 0.f, 0.f, 0.f);
    float4 xm1 = (t0 >= 1) ? *reinterpret_cast<const float4*>(g_xz + (size_t)(rowbase - 1) * (2 * D_INNER) + d4)
                           : make_float4(0.f, 0.f, 0.f, 0.f);

    #pragma unroll 4
    for (int t = 0; t < CONV_TSEG; t++) {
        const float4 x0 = *reinterpret_cast<const float4*>(
            g_xz + (size_t)(rowbase + t) * (2 * D_INNER) + d4);
        float4 o;
        {
            float a0 = bias.x;
            a0 = fmaf(xm3.x, W[0].x, a0); a0 = fmaf(xm2.x, W[0].y, a0);
            a0 = fmaf(xm1.x, W[0].z, a0); a0 = fmaf(x0.x,  W[0].w, a0);
            o.x = a0 * sigmoidf_(a0);
            float a1 = bias.y;
            a1 = fmaf(xm3.y, W[1].x, a1); a1 = fmaf(xm2.y, W[1].y, a1);
            a1 = fmaf(xm1.y, W[1].z, a1); a1 = fmaf(x0.y,  W[1].w, a1);
            o.y = a1 * sigmoidf_(a1);
            float a2 = bias.z;
            a2 = fmaf(xm3.z, W[2].x, a2); a2 = fmaf(xm2.z, W[2].y, a2);
            a2 = fmaf(xm1.z, W[2].z, a2); a2 = fmaf(x0.z,  W[2].w, a2);
            o.z = a2 * sigmoidf_(a2);
            float a3 = bias.w;
            a3 = fmaf(xm3.w, W[3].x, a3); a3 = fmaf(xm2.w, W[3].y, a3);
            a3 = fmaf(xm1.w, W[3].z, a3); a3 = fmaf(x0.w,  W[3].w, a3);
            o.w = a3 * sigmoidf_(a3);
        }
        *reinterpret_cast<float4*>(g_u + (size_t)(rowbase + t) * D_INNER + d4) = o;
        xm3 = xm2; xm2 = xm1; xm1 = x0;
    }
}

// ---------------------------------------------------------------------------
// K5: x_dbl = u @ W_x  [2048,2048]x[2048,96] — smem-staged Wx + transposed u.
// ---------------------------------------------------------------------------
#define XDBL_RPB 8
#define XDBL_KC  64
#define XDBL_UP  12
__global__ void __launch_bounds__(128) xdbl_kernel(const float* __restrict__ Wx) {
    __shared__ __align__(16) float ws[XDBL_KC * XDBL_W];     // 24 KB
    __shared__ __align__(16) float us[XDBL_KC * XDBL_UP];    //  3 KB
    const int tid = threadIdx.x;
    const int row0 = blockIdx.x * XDBL_RPB;

    float acc[XDBL_RPB];
    #pragma unroll
    for (int r = 0; r < XDBL_RPB; r++) acc[r] = 0.f;

    const int ur = tid >> 4;
    const int uk = (tid & 15) * 4;

    for (int k0 = 0; k0 < D_INNER; k0 += XDBL_KC) {
        __syncthreads();
        const float4* wsrc = reinterpret_cast<const float4*>(Wx + (size_t)k0 * XDBL_W);
        #pragma unroll
        for (int i = tid; i < (XDBL_KC * XDBL_W) / 4; i += 128)
            reinterpret_cast<float4*>(ws)[i] = wsrc[i];
        {
            float4 v = *reinterpret_cast<const float4*>(
                g_u + (size_t)(row0 + ur) * D_INNER + k0 + uk);
            us[(uk + 0) * XDBL_UP + ur] = v.x;
            us[(uk + 1) * XDBL_UP + ur] = v.y;
            us[(uk + 2) * XDBL_UP + ur] = v.z;
            us[(uk + 3) * XDBL_UP + ur] = v.w;
        }
        __syncthreads();
        if (tid < XDBL_W) {
            #pragma unroll 8
            for (int k = 0; k < XDBL_KC; k++) {
                const float w  = ws[k * XDBL_W + tid];
                const float4 ua = *reinterpret_cast<const float4*>(&us[k * XDBL_UP + 0]);
                const float4 ub = *reinterpret_cast<const float4*>(&us[k * XDBL_UP + 4]);
                acc[0] = fmaf(ua.x, w, acc[0]);
                acc[1] = fmaf(ua.y, w, acc[1]);
                acc[2] = fmaf(ua.z, w, acc[2]);
                acc[3] = fmaf(ua.w, w, acc[3]);
                acc[4] = fmaf(ub.x, w, acc[4]);
                acc[5] = fmaf(ub.y, w, acc[5]);
                acc[6] = fmaf(ub.z, w, acc[6]);
                acc[7] = fmaf(ub.w, w, acc[7]);
            }
        }
    }
    if (tid < DT_RANK) {
        #pragma unroll
        for (int r = 0; r < XDBL_RPB; r++) {
            __nv_bfloat16 hi, lo;
            split_bf16(acc[r], hi, lo);
            g_dtr_hi[(size_t)(row0 + r) * DT_RANK + tid] = hi;
            g_dtr_lo[(size_t)(row0 + r) * DT_RANK + tid] = lo;
        }
    } else if (tid < XDBL_W) {
        #pragma unroll
        for (int r = 0; r < XDBL_RPB; r++)
            g_xdbl[(size_t)(row0 + r) * XDBL_W + tid] = acc[r];
    }
}

// ---------------------------------------------------------------------------
// K7: SSM scan, cp.async-staged chunks of 16 timesteps, double-buffered.
// ---------------------------------------------------------------------------
#define SC_TC 16
struct ScanSmem {
    float dt[2][SC_TC][32];
    float u [2][SC_TC][32];
    float z [2][SC_TC][32];
    float B [2][SC_TC][16];
    float C [2][SC_TC][16];
    float y [SC_TC][32];
};

__device__ __forceinline__ void scan_prefetch(ScanSmem* ss, uint32_t sb, int buf,
                                              int rowbase, int t0, int d0, int tid) {
    const uint32_t dt_b = sb + (uint32_t)((char*)&ss->dt[buf][0][0] - (char*)ss);
    const uint32_t u_b  = sb + (uint32_t)((char*)&ss->u [buf][0][0] - (char*)ss);
    const uint32_t z_b  = sb + (uint32_t)((char*)&ss->z [buf][0][0] - (char*)ss);
    const uint32_t B_b  = sb + (uint32_t)((char*)&ss->B [buf][0][0] - (char*)ss);
    const uint32_t C_b  = sb + (uint32_t)((char*)&ss->C [buf][0][0] - (char*)ss);

    if (tid < 128) {
        const int r = tid >> 3, c = tid & 7;
        CP_ASYNC_16(dt_b + (r * 32 + c * 4) * 4,
                    g_dt + (size_t)(rowbase + t0 + r) * D_INNER + d0 + c * 4);
    } else if (tid < 256) {
        const int i = tid - 128;
        const int r = i >> 3, c = i & 7;
        CP_ASYNC_16(u_b + (r * 32 + c * 4) * 4,
                    g_u + (size_t)(rowbase + t0 + r) * D_INNER + d0 + c * 4);
    } else if (tid < 384) {
        const int i = tid - 256;
        const int r = i >> 3, c = i & 7;
        CP_ASYNC_16(z_b + (r * 32 + c * 4) * 4,
                    g_xz + (size_t)(rowbase + t0 + r) * (2 * D_INNER) + D_INNER + d0 + c * 4);
    } else if (tid < 448) {
        const int i = tid - 384;
        const int r = i >> 2, c = i & 3;
        CP_ASYNC_16(B_b + (r * 16 + c * 4) * 4,
                    g_xdbl + (size_t)(rowbase + t0 + r) * XDBL_W + DT_RANK + c * 4);
    } else {
        const int i = tid - 448;
        const int r = i >> 2, c = i & 3;
        CP_ASYNC_16(C_b + (r * 16 + c * 4) * 4,
                    g_xdbl + (size_t)(rowbase + t0 + r) * XDBL_W + DT_RANK + D_STATE + c * 4);
    }
}

__global__ void __launch_bounds__(512) scan_kernel(const float* __restrict__ A_log,
                                                   const float* __restrict__ Dskip) {
    __shared__ ScanSmem ss;
    const uint32_t sb = smem_to_u32(&ss);
    const int tid  = threadIdx.x;
    const int n    = tid & 15;
    const int dloc = tid >> 4;
    const int b    = blockIdx.x >> 6;
    const int dblk = blockIdx.x & 63;
    const int d0   = dblk * 32;
    const int d    = d0 + dloc;
    const int rowbase = b * SEQ;

    const float a   = -__expf(A_log[d * D_STATE + n]);
    const float dsk = Dskip[d];

    float hstate = 0.f;

    scan_prefetch(&ss, sb, 0, rowbase, 0, d0, tid);
    CP_COMMIT();

    const int NCH = SEQ / SC_TC;
    for (int c = 0; c < NCH; c++) {
        const int buf = c & 1;
        if (c + 1 < NCH) {
            scan_prefetch(&ss, sb, buf ^ 1, rowbase, (c + 1) * SC_TC, d0, tid);
            CP_COMMIT();
            CP_WAIT(1);
        } else {
            CP_WAIT(0);
        }
        __syncthreads();

        #pragma unroll
        for (int i = 0; i < SC_TC; i++) {
            const float dtv = ss.dt[buf][i][dloc];
            const float uv  = ss.u [buf][i][dloc];
            const float Bv  = ss.B [buf][i][n];
            const float Cv  = ss.C [buf][i][n];

            const float dA = __expf(dtv * a);
            hstate = fmaf(dA, hstate, (dtv * uv) * Bv);
            float p = hstate * Cv;
            p += __shfl_xor_sync(0xffffffffu, p, 1);
            p += __shfl_xor_sync(0xffffffffu, p, 2);
            p += __shfl_xor_sync(0xffffffffu, p, 4);
            p += __shfl_xor_sync(0xffffffffu, p, 8);
            if (n == 0) {
                const float zv = ss.z[buf][i][dloc];
                ss.y[i][dloc] = (p + uv * dsk) * (zv * sigmoidf_(zv));
            }
        }
        __syncthreads();

        {
            const int it = tid >> 5;
            const int dd = tid & 31;
            const float yv = ss.y[it][dd];
            __nv_bfloat16 hi, lo;
            split_bf16(yv, hi, lo);
            const size_t idx = (size_t)(rowbase + c * SC_TC + it) * D_INNER + d0 + dd;
            g_yhi[idx] = hi;
            g_ylo[idx] = lo;
        }
    }
}

// ---------------------------------------------------------------------------
// Launch  (4th launch = conv_silu_kernel for ncu instrumentation)
// ---------------------------------------------------------------------------
extern "C" void kernel_launch(void* const* d_in, const int* in_sizes, int n_in,
                              void* d_out, int out_size) {
    const float* x      = (const float*)d_in[0];
    const float* gamma  = (const float*)d_in[1];
    const float* beta   = (const float*)d_in[2];
    const float* W_in   = (const float*)d_in[3];
    const float* W_conv = (const float*)d_in[4];
    const float* b_conv = (const float*)d_in[5];
    const float* W_x    = (const float*)d_in[6];
    const float* W_dt   = (const float*)d_in[7];
    const float* b_dt   = (const float*)d_in[8];
    const float* A_log  = (const float*)d_in[9];
    const float* Dskip  = (const float*)d_in[10];
    const float* W_out  = (const float*)d_in[11];
    float* out = (float*)d_out;

    float *xz, *u, *xdbl, *dt;
    cudaGetSymbolAddress((void**)&xz,   g_xz);
    cudaGetSymbolAddress((void**)&u,    g_u);
    cudaGetSymbolAddress((void**)&xdbl, g_xdbl);
    cudaGetSymbolAddress((void**)&dt,   g_dt);
    __nv_bfloat16 *hhi, *hlo, *winthi, *wintlo, *yhi, *ylo, *wothi, *wotlo;
    __nv_bfloat16 *dtrhi, *dtrlo, *wdtthi, *wdttlo;
    cudaGetSymbolAddress((void**)&hhi,    g_hhi);
    cudaGetSymbolAddress((void**)&hlo,    g_hlo);
    cudaGetSymbolAddress((void**)&winthi, g_wint_hi);
    cudaGetSymbolAddress((void**)&wintlo, g_wint_lo);
    cudaGetSymbolAddress((void**)&yhi,    g_yhi);
    cudaGetSymbolAddress((void**)&ylo,    g_ylo);
    cudaGetSymbolAddress((void**)&wothi,  g_wot_hi);
    cudaGetSymbolAddress((void**)&wotlo,  g_wot_lo);
    cudaGetSymbolAddress((void**)&dtrhi,  g_dtr_hi);
    cudaGetSymbolAddress((void**)&dtrlo,  g_dtr_lo);
    cudaGetSymbolAddress((void**)&wdtthi, g_wdtt_hi);
    cudaGetSymbolAddress((void**)&wdttlo, g_wdtt_lo);

    cudaFuncSetAttribute(bf16split_gemm<128,false>, cudaFuncAttributeMaxDynamicSharedMemorySize, GT_SMEM_128);
    cudaFuncSetAttribute(bf16split_gemm<128,true >, cudaFuncAttributeMaxDynamicSharedMemorySize, GT_SMEM_128);

    // 1: LayerNorm -> bf16 split h
    ln_kernel<<<ROWS, 256>>>(x, gamma, beta);

    // 2: W_in transpose+split
    transpose_split_kernel<<<dim3((2*D_INNER)/32, D_MODEL/32), dim3(32, 8)>>>(
        W_in, D_MODEL, 2*D_INNER, winthi, wintlo);

    // 3: xz = h @ W_in   (HMMA bf16-split, 4-stage)
    bf16split_gemm<128,false><<<dim3((2*D_INNER)/128, ROWS/128), 256, GT_SMEM_128>>>(
        hhi, hlo, winthi, wintlo, xz, nullptr, nullptr, ROWS, 2*D_INNER, D_MODEL);

    // 4: u = silu(depthwise_conv(xi) + b_conv)   <-- ncu capture slot
    conv_silu_kernel<<<dim3(D_INNER/512, SEQ/CONV_TSEG, BATCH), 128>>>(W_conv, b_conv);

    // 5: x_dbl = u @ W_x  (smem-staged)
    xdbl_kernel<<<ROWS/XDBL_RPB, 128>>>(W_x);

    // 6: W_dt transpose+split
    transpose_split_kernel<<<dim3(D_INNER/32, DT_RANK/32), dim3(32, 8)>>>(
        W_dt, DT_RANK, D_INNER, wdtthi, wdttlo);

    // 7: dt = softplus(dt_r @ W_dt + b_dt)   (HMMA bf16-split, 4-stage)
    bf16split_gemm<128,true><<<dim3(D_INNER/128, ROWS/128), 256, GT_SMEM_128>>>(
        dtrhi, dtrlo, wdtthi, wdttlo, dt, nullptr, b_dt, ROWS, D_INNER, DT_RANK);

    // 8: sequential scan + Dskip + silu(z) gate -> bf16 split y
    scan_kernel<<<BATCH * (D_INNER/32), 512>>>(A_log, Dskip);

    // 9: W_out transpose+split
    transpose_split_kernel<<<dim3(D_MODEL/32, D_INNER/32), dim3(32, 8)>>>(
        W_out, D_INNER, D_MODEL, wothi, wotlo);

    // 10: out = x + y @ W_out  (HMMA bf16-split, BM=128, 4-stage)
    bf16split_gemm<128,false><<<dim3(D_MODEL/128, ROWS/128), 256, GT_SMEM_128>>>(
        yhi, ylo, wothi, wotlo, out, x, nullptr, ROWS, D_MODEL, D_INNER);
}

// round 13
// speedup vs baseline: 1.0715x; 1.0715x over previous
#include <cuda_runtime.h>
#include <cuda_bf16.h>
#include <cstdint>
#include <math.h>

// Problem constants
#define D_MODEL  1024
#define D_INNER  2048
#define D_STATE  16
#define D_CONV   4
#define DT_RANK  64
#define BATCH    2
#define SEQ      1024
#define ROWS     (BATCH*SEQ)           // 2048
#define XDBL_W   (DT_RANK + 2*D_STATE) // 96

// ---------------------------------------------------------------------------
// Scratch (static device arrays; no allocation allowed)
// ---------------------------------------------------------------------------
__device__ float g_xz  [ROWS * 2 * D_INNER];    // [xi | z]
__device__ float g_u   [ROWS * D_INNER];
__device__ float g_xdbl[ROWS * XDBL_W];         // [dt_r | B | C] (B,C used by scan)
__device__ float g_dt  [ROWS * D_INNER];

// bf16 split operands for tensor-core GEMMs
__device__ __nv_bfloat16 g_hhi [ROWS * D_MODEL];
__device__ __nv_bfloat16 g_hlo [ROWS * D_MODEL];
__device__ __nv_bfloat16 g_wint_hi[(2*D_INNER) * D_MODEL]; // W_in^T  [4096,1024]
__device__ __nv_bfloat16 g_wint_lo[(2*D_INNER) * D_MODEL];
__device__ __nv_bfloat16 g_yhi [ROWS * D_INNER];
__device__ __nv_bfloat16 g_ylo [ROWS * D_INNER];
__device__ __nv_bfloat16 g_wot_hi[D_MODEL * D_INNER];      // W_out^T [1024,2048]
__device__ __nv_bfloat16 g_wot_lo[D_MODEL * D_INNER];
__device__ __nv_bfloat16 g_dtr_hi[ROWS * DT_RANK];         // dt_r split [2048,64]
__device__ __nv_bfloat16 g_dtr_lo[ROWS * DT_RANK];
__device__ __nv_bfloat16 g_wdtt_hi[D_INNER * DT_RANK];     // W_dt^T [2048,64]
__device__ __nv_bfloat16 g_wdtt_lo[D_INNER * DT_RANK];

// ---------------------------------------------------------------------------
// PTX helpers (sm_80-era only: ldmatrix / mma.sync / cp.async)
// ---------------------------------------------------------------------------
__device__ __forceinline__ uint32_t smem_to_u32(const void* p) {
    uint32_t a;
    asm("{ .reg .u64 t; cvta.to.shared.u64 t, %1; cvt.u32.u64 %0, t; }" : "=r"(a) : "l"(p));
    return a;
}
#define CP_ASYNC_16(dst_u32, src_ptr) \
    asm volatile("cp.async.cg.shared.global [%0], [%1], 16;" :: "r"(dst_u32), "l"(src_ptr))
#define CP_COMMIT() asm volatile("cp.async.commit_group;" ::: "memory")
#define CP_WAIT(n)  asm volatile("cp.async.wait_group %0;" :: "n"(n) : "memory")

#define LDSM_X4(r0,r1,r2,r3,addr) \
    asm volatile("ldmatrix.sync.aligned.m8n8.x4.shared.b16 {%0,%1,%2,%3}, [%4];" \
        : "=r"(r0),"=r"(r1),"=r"(r2),"=r"(r3) : "r"(addr))

__device__ __forceinline__ void mma_bf16(float* c, const uint32_t* a, const uint32_t* b) {
    asm volatile(
        "mma.sync.aligned.m16n8k16.row.col.f32.bf16.bf16.f32 "
        "{%0,%1,%2,%3}, {%4,%5,%6,%7}, {%8,%9}, {%0,%1,%2,%3};"
        : "+f"(c[0]), "+f"(c[1]), "+f"(c[2]), "+f"(c[3])
        : "r"(a[0]), "r"(a[1]), "r"(a[2]), "r"(a[3]), "r"(b[0]), "r"(b[1]));
}

// ---------------------------------------------------------------------------
// Math helpers
// ---------------------------------------------------------------------------
__device__ __forceinline__ float sigmoidf_(float x) { return 1.0f / (1.0f + __expf(-x)); }
__device__ __forceinline__ float softplusf_(float x) {
    return fmaxf(x, 0.0f) + log1pf(__expf(-fabsf(x)));
}
__device__ __forceinline__ void split_bf16(float v, __nv_bfloat16& hi, __nv_bfloat16& lo) {
    hi = __float2bfloat16(v);
    lo = __float2bfloat16(v - __bfloat162float(hi));
}

// ---------------------------------------------------------------------------
// K1: LayerNorm -> bf16-split (g_hhi / g_hlo)
// ---------------------------------------------------------------------------
__global__ void ln_kernel(const float* __restrict__ x,
                          const float* __restrict__ gamma,
                          const float* __restrict__ beta) {
    const int row = blockIdx.x;
    const int tid = threadIdx.x;
    const float4* xv = reinterpret_cast<const float4*>(x + (size_t)row * D_MODEL);
    float4 v = xv[tid];
    float s  = v.x + v.y + v.z + v.w;
    float s2 = v.x*v.x + v.y*v.y + v.z*v.z + v.w*v.w;

    #pragma unroll
    for (int o = 16; o > 0; o >>= 1) {
        s  += __shfl_xor_sync(0xffffffffu, s,  o);
        s2 += __shfl_xor_sync(0xffffffffu, s2, o);
    }
    __shared__ float red0[8], red1[8];
    const int wid = tid >> 5, lane = tid & 31;
    if (lane == 0) { red0[wid] = s; red1[wid] = s2; }
    __syncthreads();
    if (wid == 0) {
        s  = (lane < 8) ? red0[lane] : 0.f;
        s2 = (lane < 8) ? red1[lane] : 0.f;
        #pragma unroll
        for (int o = 4; o > 0; o >>= 1) {
            s  += __shfl_xor_sync(0xffffffffu, s,  o);
            s2 += __shfl_xor_sync(0xffffffffu, s2, o);
        }
        if (lane == 0) { red0[0] = s; red1[0] = s2; }
    }
    __syncthreads();
    const float mean = red0[0] * (1.0f / D_MODEL);
    const float var  = red1[0] * (1.0f / D_MODEL) - mean * mean;
    const float rstd = rsqrtf(var + 1e-5f);

    const float4 g  = reinterpret_cast<const float4*>(gamma)[tid];
    const float4 be = reinterpret_cast<const float4*>(beta)[tid];
    float o[4];
    o[0] = (v.x - mean) * rstd * g.x + be.x;
    o[1] = (v.y - mean) * rstd * g.y + be.y;
    o[2] = (v.z - mean) * rstd * g.z + be.z;
    o[3] = (v.w - mean) * rstd * g.w + be.w;
    const size_t base = (size_t)row * D_MODEL + tid * 4;
    #pragma unroll
    for (int j = 0; j < 4; j++) {
        __nv_bfloat16 hi, lo;
        split_bf16(o[j], hi, lo);
        g_hhi[base + j] = hi;
        g_hlo[base + j] = lo;
    }
}

// ---------------------------------------------------------------------------
// K2: tiled transpose + bf16-split: in[R,C] fp32 -> out[C,R] (hi,lo)
// ---------------------------------------------------------------------------
__global__ void transpose_split_kernel(const float* __restrict__ in, int R, int C,
                                       __nv_bfloat16* __restrict__ outhi,
                                       __nv_bfloat16* __restrict__ outlo) {
    __shared__ float tile[32][33];
    const int c0 = blockIdx.x * 32;
    const int r0 = blockIdx.y * 32;
    const int tx = threadIdx.x, ty = threadIdx.y;   // 32 x 8
    #pragma unroll
    for (int i = 0; i < 32; i += 8)
        tile[ty + i][tx] = in[(size_t)(r0 + ty + i) * C + c0 + tx];
    __syncthreads();
    #pragma unroll
    for (int i = 0; i < 32; i += 8) {
        float v = tile[tx][ty + i];
        __nv_bfloat16 hi, lo;
        split_bf16(v, hi, lo);
        size_t oidx = (size_t)(c0 + ty + i) * R + r0 + tx;
        outhi[oidx] = hi;
        outlo[oidx] = lo;
    }
}

// ---------------------------------------------------------------------------
// K3: bf16-split GEMM via mma.sync — 2-stage (80KB => 2 CTAs/SM; measured best)
//   C[M,N] = op(Ahi@B^T(3-term) [+bias][softplus]) [+ Cadd]
// ---------------------------------------------------------------------------
#define GT_ROWB    80

template<int BMROWS>
__device__ __forceinline__ void tile_cp_async(uint32_t smem_tile,
                                              const __nv_bfloat16* __restrict__ src,
                                              int ldk, int tid) {
    #pragma unroll
    for (int i = tid; i < BMROWS * 4; i += 256) {
        const int row   = i >> 2;
        const int chunk = i & 3;
        const __nv_bfloat16* g = src + (size_t)row * ldk + chunk * 8;
        CP_ASYNC_16(smem_tile + row * GT_ROWB + chunk * 16, g);
    }
}

template<int BM, bool SOFTPLUS>
__global__ void __launch_bounds__(256)
bf16split_gemm(const __nv_bfloat16* __restrict__ Ahi, const __nv_bfloat16* __restrict__ Alo,
               const __nv_bfloat16* __restrict__ Bhi, const __nv_bfloat16* __restrict__ Blo,
               float* __restrict__ C, const float* __restrict__ Cadd,
               const float* __restrict__ bias,
               int M, int N, int K) {
    constexpr int MI      = BM / 32;                 // m-fragments per warp
    constexpr int A_TILE  = BM * GT_ROWB;
    constexpr int B_TILE  = 128 * GT_ROWB;
    constexpr int ST_AHI  = 0;
    constexpr int ST_ALO  = ST_AHI + A_TILE;
    constexpr int ST_BHI  = ST_ALO + A_TILE;
    constexpr int ST_BLO  = ST_BHI + B_TILE;
    constexpr int STAGE   = 2 * A_TILE + 2 * B_TILE;

    extern __shared__ char smem[];
    const uint32_t sbase = smem_to_u32(smem);
    const int tid = threadIdx.x;
    const int wid = tid >> 5, L = tid & 31;
    const int wm = wid & 1;
    const int wn = wid >> 1;
    const int m0 = blockIdx.y * BM;
    const int n0 = blockIdx.x * 128;

    const uint32_t a_lane = (uint32_t)((wm * (BM / 2) + (L & 15)) * GT_ROWB + (L >> 4) * 16);
    const uint32_t b_lane = (uint32_t)((wn * 32 + (L & 7) + ((L >> 4) << 3)) * GT_ROWB
                                       + ((L >> 3) & 1) * 16);

    float acc[MI][4][4];
    #pragma unroll
    for (int i = 0; i < MI; i++)
        #pragma unroll
        for (int j = 0; j < 4; j++)
            #pragma unroll
            for (int k = 0; k < 4; k++) acc[i][j][k] = 0.f;

    const int NC = K >> 5;
    const size_t abase = (size_t)m0 * K;
    const size_t bbase = (size_t)n0 * K;

    {
        tile_cp_async<BM >(sbase + ST_AHI, Ahi + abase, K, tid);
        tile_cp_async<BM >(sbase + ST_ALO, Alo + abase, K, tid);
        tile_cp_async<128>(sbase + ST_BHI, Bhi + bbase, K, tid);
        tile_cp_async<128>(sbase + ST_BLO, Blo + bbase, K, tid);
        CP_COMMIT();
    }

    for (int c = 0; c < NC; c++) {
        const uint32_t stage = sbase + (c & 1) * STAGE;

        if (c + 1 < NC) {
            const uint32_t nstage = sbase + ((c + 1) & 1) * STAGE;
            const int kc = (c + 1) << 5;
            tile_cp_async<BM >(nstage + ST_AHI, Ahi + abase + kc, K, tid);
            tile_cp_async<BM >(nstage + ST_ALO, Alo + abase + kc, K, tid);
            tile_cp_async<128>(nstage + ST_BHI, Bhi + bbase + kc, K, tid);
            tile_cp_async<128>(nstage + ST_BLO, Blo + bbase + kc, K, tid);
            CP_COMMIT();
            CP_WAIT(1);
        } else {
            CP_WAIT(0);
        }
        __syncthreads();

        const uint32_t sAhi = stage + ST_AHI + a_lane;
        const uint32_t sAlo = stage + ST_ALO + a_lane;
        const uint32_t sBhi = stage + ST_BHI + b_lane;
        const uint32_t sBlo = stage + ST_BLO + b_lane;

        #pragma unroll
        for (int ks = 0; ks < 2; ks++) {
            uint32_t bh[8], bl[8];
            LDSM_X4(bh[0], bh[1], bh[2], bh[3], sBhi + 0 * 16 * GT_ROWB + ks * 32);
            LDSM_X4(bh[4], bh[5], bh[6], bh[7], sBhi + 1 * 16 * GT_ROWB + ks * 32);
            LDSM_X4(bl[0], bl[1], bl[2], bl[3], sBlo + 0 * 16 * GT_ROWB + ks * 32);
            LDSM_X4(bl[4], bl[5], bl[6], bl[7], sBlo + 1 * 16 * GT_ROWB + ks * 32);
            #pragma unroll
            for (int mi = 0; mi < MI; mi++) {
                uint32_t ah[4], al[4];
                LDSM_X4(ah[0], ah[1], ah[2], ah[3], sAhi + mi * 16 * GT_ROWB + ks * 32);
                LDSM_X4(al[0], al[1], al[2], al[3], sAlo + mi * 16 * GT_ROWB + ks * 32);
                #pragma unroll
                for (int ni = 0; ni < 4; ni++) {
                    mma_bf16(acc[mi][ni], ah, &bh[ni * 2]);
                    mma_bf16(acc[mi][ni], ah, &bl[ni * 2]);
                    mma_bf16(acc[mi][ni], al, &bh[ni * 2]);
                }
            }
        }
        __syncthreads();
    }

    const int g  = L >> 2;
    const int tg = L & 3;
    #pragma unroll
    for (int mi = 0; mi < MI; mi++) {
        const int r0 = m0 + wm * (BM / 2) + mi * 16 + g;
        #pragma unroll
        for (int ni = 0; ni < 4; ni++) {
            const int cc = n0 + wn * 32 + ni * 8 + tg * 2;
            float2 v0 = make_float2(acc[mi][ni][0], acc[mi][ni][1]);
            float2 v1 = make_float2(acc[mi][ni][2], acc[mi][ni][3]);
            if (bias) {
                const float2 bv = *reinterpret_cast<const float2*>(bias + cc);
                v0.x += bv.x; v0.y += bv.y;
                v1.x += bv.x; v1.y += bv.y;
            }
            if (SOFTPLUS) {
                v0.x = softplusf_(v0.x); v0.y = softplusf_(v0.y);
                v1.x = softplusf_(v1.x); v1.y = softplusf_(v1.y);
            }
            if (Cadd) {
                const float2 a0 = *reinterpret_cast<const float2*>(Cadd + (size_t)r0 * N + cc);
                const float2 a1 = *reinterpret_cast<const float2*>(Cadd + (size_t)(r0 + 8) * N + cc);
                v0.x += a0.x; v0.y += a0.y;
                v1.x += a1.x; v1.y += a1.y;
            }
            *reinterpret_cast<float2*>(C + (size_t)r0 * N + cc)       = v0;
            *reinterpret_cast<float2*>(C + (size_t)(r0 + 8) * N + cc) = v1;
        }
    }
}

#define GT_SMEM_128  (2 * (2 * 128 * GT_ROWB + 2 * 128 * GT_ROWB))   // 81920
#define GT_SMEM_64   (2 * (2 * 64  * GT_ROWB + 2 * 128 * GT_ROWB))   // 61440

// ---------------------------------------------------------------------------
// K4: depthwise causal conv + bias + silu — float4 lanes AND 512 CTAs.
//   grid (D_INNER/512, SEQ/CONV_TSEG, BATCH) = (4, 64, 2) = 512 blocks.
// ---------------------------------------------------------------------------
#define CONV_TSEG 16
__global__ void __launch_bounds__(128) conv_silu_kernel(const float* __restrict__ Wc,
                                                        const float* __restrict__ bc) {
    const int d4 = (blockIdx.x * 128 + threadIdx.x) * 4;   // 4 consecutive d
    const int t0 = blockIdx.y * CONV_TSEG;
    const int b  = blockIdx.z;
    const int rowbase = b * SEQ + t0;

    float4 W[4];
    #pragma unroll
    for (int j = 0; j < 4; j++)
        W[j] = *reinterpret_cast<const float4*>(Wc + (size_t)(d4 + j) * D_CONV);
    const float4 bias = *reinterpret_cast<const float4*>(bc + d4);

    float4 xm3 = (t0 >= 3) ? *reinterpret_cast<const float4*>(g_xz + (size_t)(rowbase - 3) * (2 * D_INNER) + d4)
                           : make_float4(0.f, 0.f, 0.f, 0.f);
    float4 xm2 = (t0 >= 2) ? *reinterpret_cast<const float4*>(g_xz + (size_t)(rowbase - 2) * (2 * D_INNER) + d4)
                           : make_float4(0.f, 0.f, 0.f, 0.f);
    float4 xm1 = (t0 >= 1) ? *reinterpret_cast<const float4*>(g_xz + (size_t)(rowbase - 1) * (2 * D_INNER) + d4)
                           : make_float4(0.f, 0.f, 0.f, 0.f);

    #pragma unroll
    for (int t = 0; t < CONV_TSEG; t++) {
        const float4 x0 = *reinterpret_cast<const float4*>(
            g_xz + (size_t)(rowbase + t) * (2 * D_INNER) + d4);
        float4 o;
        {
            float a0 = bias.x;
            a0 = fmaf(xm3.x, W[0].x, a0); a0 = fmaf(xm2.x, W[0].y, a0);
            a0 = fmaf(xm1.x, W[0].z, a0); a0 = fmaf(x0.x,  W[0].w, a0);
            o.x = a0 * sigmoidf_(a0);
            float a1 = bias.y;
            a1 = fmaf(xm3.y, W[1].x, a1); a1 = fmaf(xm2.y, W[1].y, a1);
            a1 = fmaf(xm1.y, W[1].z, a1); a1 = fmaf(x0.y,  W[1].w, a1);
            o.y = a1 * sigmoidf_(a1);
            float a2 = bias.z;
            a2 = fmaf(xm3.z, W[2].x, a2); a2 = fmaf(xm2.z, W[2].y, a2);
            a2 = fmaf(xm1.z, W[2].z, a2); a2 = fmaf(x0.z,  W[2].w, a2);
            o.z = a2 * sigmoidf_(a2);
            float a3 = bias.w;
            a3 = fmaf(xm3.w, W[3].x, a3); a3 = fmaf(xm2.w, W[3].y, a3);
            a3 = fmaf(xm1.w, W[3].z, a3); a3 = fmaf(x0.w,  W[3].w, a3);
            o.w = a3 * sigmoidf_(a3);
        }
        *reinterpret_cast<float4*>(g_u + (size_t)(rowbase + t) * D_INNER + d4) = o;
        xm3 = xm2; xm2 = xm1; xm1 = x0;
    }
}

// ---------------------------------------------------------------------------
// K5: x_dbl = u @ W_x  [2048,2048]x[2048,96] — smem-staged Wx + transposed u.
// ---------------------------------------------------------------------------
#define XDBL_RPB 8
#define XDBL_KC  64
#define XDBL_UP  12
__global__ void __launch_bounds__(128) xdbl_kernel(const float* __restrict__ Wx) {
    __shared__ __align__(16) float ws[XDBL_KC * XDBL_W];     // 24 KB
    __shared__ __align__(16) float us[XDBL_KC * XDBL_UP];    //  3 KB
    const int tid = threadIdx.x;
    const int row0 = blockIdx.x * XDBL_RPB;

    float acc[XDBL_RPB];
    #pragma unroll
    for (int r = 0; r < XDBL_RPB; r++) acc[r] = 0.f;

    const int ur = tid >> 4;
    const int uk = (tid & 15) * 4;

    for (int k0 = 0; k0 < D_INNER; k0 += XDBL_KC) {
        __syncthreads();
        const float4* wsrc = reinterpret_cast<const float4*>(Wx + (size_t)k0 * XDBL_W);
        #pragma unroll
        for (int i = tid; i < (XDBL_KC * XDBL_W) / 4; i += 128)
            reinterpret_cast<float4*>(ws)[i] = wsrc[i];
        {
            float4 v = *reinterpret_cast<const float4*>(
                g_u + (size_t)(row0 + ur) * D_INNER + k0 + uk);
            us[(uk + 0) * XDBL_UP + ur] = v.x;
            us[(uk + 1) * XDBL_UP + ur] = v.y;
            us[(uk + 2) * XDBL_UP + ur] = v.z;
            us[(uk + 3) * XDBL_UP + ur] = v.w;
        }
        __syncthreads();
        if (tid < XDBL_W) {
            #pragma unroll 8
            for (int k = 0; k < XDBL_KC; k++) {
                const float w  = ws[k * XDBL_W + tid];
                const float4 ua = *reinterpret_cast<const float4*>(&us[k * XDBL_UP + 0]);
                const float4 ub = *reinterpret_cast<const float4*>(&us[k * XDBL_UP + 4]);
                acc[0] = fmaf(ua.x, w, acc[0]);
                acc[1] = fmaf(ua.y, w, acc[1]);
                acc[2] = fmaf(ua.z, w, acc[2]);
                acc[3] = fmaf(ua.w, w, acc[3]);
                acc[4] = fmaf(ub.x, w, acc[4]);
                acc[5] = fmaf(ub.y, w, acc[5]);
                acc[6] = fmaf(ub.z, w, acc[6]);
                acc[7] = fmaf(ub.w, w, acc[7]);
            }
        }
    }
    if (tid < DT_RANK) {
        #pragma unroll
        for (int r = 0; r < XDBL_RPB; r++) {
            __nv_bfloat16 hi, lo;
            split_bf16(acc[r], hi, lo);
            g_dtr_hi[(size_t)(row0 + r) * DT_RANK + tid] = hi;
            g_dtr_lo[(size_t)(row0 + r) * DT_RANK + tid] = lo;
        }
    } else if (tid < XDBL_W) {
        #pragma unroll
        for (int r = 0; r < XDBL_RPB; r++)
            g_xdbl[(size_t)(row0 + r) * XDBL_W + tid] = acc[r];
    }
}

// ---------------------------------------------------------------------------
// K7: SSM scan, cp.async-staged chunks of 16 timesteps, double-buffered.
// ---------------------------------------------------------------------------
#define SC_TC 16
struct ScanSmem {
    float dt[2][SC_TC][32];
    float u [2][SC_TC][32];
    float z [2][SC_TC][32];
    float B [2][SC_TC][16];
    float C [2][SC_TC][16];
    float y [SC_TC][32];
};

__device__ __forceinline__ void scan_prefetch(ScanSmem* ss, uint32_t sb, int buf,
                                              int rowbase, int t0, int d0, int tid) {
    const uint32_t dt_b = sb + (uint32_t)((char*)&ss->dt[buf][0][0] - (char*)ss);
    const uint32_t u_b  = sb + (uint32_t)((char*)&ss->u [buf][0][0] - (char*)ss);
    const uint32_t z_b  = sb + (uint32_t)((char*)&ss->z [buf][0][0] - (char*)ss);
    const uint32_t B_b  = sb + (uint32_t)((char*)&ss->B [buf][0][0] - (char*)ss);
    const uint32_t C_b  = sb + (uint32_t)((char*)&ss->C [buf][0][0] - (char*)ss);

    if (tid < 128) {
        const int r = tid >> 3, c = tid & 7;
        CP_ASYNC_16(dt_b + (r * 32 + c * 4) * 4,
                    g_dt + (size_t)(rowbase + t0 + r) * D_INNER + d0 + c * 4);
    } else if (tid < 256) {
        const int i = tid - 128;
        const int r = i >> 3, c = i & 7;
        CP_ASYNC_16(u_b + (r * 32 + c * 4) * 4,
                    g_u + (size_t)(rowbase + t0 + r) * D_INNER + d0 + c * 4);
    } else if (tid < 384) {
        const int i = tid - 256;
        const int r = i >> 3, c = i & 7;
        CP_ASYNC_16(z_b + (r * 32 + c * 4) * 4,
                    g_xz + (size_t)(rowbase + t0 + r) * (2 * D_INNER) + D_INNER + d0 + c * 4);
    } else if (tid < 448) {
        const int i = tid - 384;
        const int r = i >> 2, c = i & 3;
        CP_ASYNC_16(B_b + (r * 16 + c * 4) * 4,
                    g_xdbl + (size_t)(rowbase + t0 + r) * XDBL_W + DT_RANK + c * 4);
    } else {
        const int i = tid - 448;
        const int r = i >> 2, c = i & 3;
        CP_ASYNC_16(C_b + (r * 16 + c * 4) * 4,
                    g_xdbl + (size_t)(rowbase + t0 + r) * XDBL_W + DT_RANK + D_STATE + c * 4);
    }
}

__global__ void __launch_bounds__(512) scan_kernel(const float* __restrict__ A_log,
                                                   const float* __restrict__ Dskip) {
    __shared__ ScanSmem ss;
    const uint32_t sb = smem_to_u32(&ss);
    const int tid  = threadIdx.x;
    const int n    = tid & 15;
    const int dloc = tid >> 4;
    const int b    = blockIdx.x >> 6;
    const int dblk = blockIdx.x & 63;
    const int d0   = dblk * 32;
    const int d    = d0 + dloc;
    const int rowbase = b * SEQ;

    const float a   = -__expf(A_log[d * D_STATE + n]);
    const float dsk = Dskip[d];

    float hstate = 0.f;

    scan_prefetch(&ss, sb, 0, rowbase, 0, d0, tid);
    CP_COMMIT();

    const int NCH = SEQ / SC_TC;
    for (int c = 0; c < NCH; c++) {
        const int buf = c & 1;
        if (c + 1 < NCH) {
            scan_prefetch(&ss, sb, buf ^ 1, rowbase, (c + 1) * SC_TC, d0, tid);
            CP_COMMIT();
            CP_WAIT(1);
        } else {
            CP_WAIT(0);
        }
        __syncthreads();

        #pragma unroll
        for (int i = 0; i < SC_TC; i++) {
            const float dtv = ss.dt[buf][i][dloc];
            const float uv  = ss.u [buf][i][dloc];
            const float Bv  = ss.B [buf][i][n];
            const float Cv  = ss.C [buf][i][n];

            const float dA = __expf(dtv * a);
            hstate = fmaf(dA, hstate, (dtv * uv) * Bv);
            float p = hstate * Cv;
            p += __shfl_xor_sync(0xffffffffu, p, 1);
            p += __shfl_xor_sync(0xffffffffu, p, 2);
            p += __shfl_xor_sync(0xffffffffu, p, 4);
            p += __shfl_xor_sync(0xffffffffu, p, 8);
            if (n == 0) {
                const float zv = ss.z[buf][i][dloc];
                ss.y[i][dloc] = (p + uv * dsk) * (zv * sigmoidf_(zv));
            }
        }
        __syncthreads();

        {
            const int it = tid >> 5;
            const int dd = tid & 31;
            const float yv = ss.y[it][dd];
            __nv_bfloat16 hi, lo;
            split_bf16(yv, hi, lo);
            const size_t idx = (size_t)(rowbase + c * SC_TC + it) * D_INNER + d0 + dd;
            g_yhi[idx] = hi;
            g_ylo[idx] = lo;
        }
    }
}

// ---------------------------------------------------------------------------
// Launch  (4th launch = conv_silu_kernel for ncu instrumentation)
// ---------------------------------------------------------------------------
extern "C" void kernel_launch(void* const* d_in, const int* in_sizes, int n_in,
                              void* d_out, int out_size) {
    const float* x      = (const float*)d_in[0];
    const float* gamma  = (const float*)d_in[1];
    const float* beta   = (const float*)d_in[2];
    const float* W_in   = (const float*)d_in[3];
    const float* W_conv = (const float*)d_in[4];
    const float* b_conv = (const float*)d_in[5];
    const float* W_x    = (const float*)d_in[6];
    const float* W_dt   = (const float*)d_in[7];
    const float* b_dt   = (const float*)d_in[8];
    const float* A_log  = (const float*)d_in[9];
    const float* Dskip  = (const float*)d_in[10];
    const float* W_out  = (const float*)d_in[11];
    float* out = (float*)d_out;

    float *xz, *u, *xdbl, *dt;
    cudaGetSymbolAddress((void**)&xz,   g_xz);
    cudaGetSymbolAddress((void**)&u,    g_u);
    cudaGetSymbolAddress((void**)&xdbl, g_xdbl);
    cudaGetSymbolAddress((void**)&dt,   g_dt);
    __nv_bfloat16 *hhi, *hlo, *winthi, *wintlo, *yhi, *ylo, *wothi, *wotlo;
    __nv_bfloat16 *dtrhi, *dtrlo, *wdtthi, *wdttlo;
    cudaGetSymbolAddress((void**)&hhi,    g_hhi);
    cudaGetSymbolAddress((void**)&hlo,    g_hlo);
    cudaGetSymbolAddress((void**)&winthi, g_wint_hi);
    cudaGetSymbolAddress((void**)&wintlo, g_wint_lo);
    cudaGetSymbolAddress((void**)&yhi,    g_yhi);
    cudaGetSymbolAddress((void**)&ylo,    g_ylo);
    cudaGetSymbolAddress((void**)&wothi,  g_wot_hi);
    cudaGetSymbolAddress((void**)&wotlo,  g_wot_lo);
    cudaGetSymbolAddress((void**)&dtrhi,  g_dtr_hi);
    cudaGetSymbolAddress((void**)&dtrlo,  g_dtr_lo);
    cudaGetSymbolAddress((void**)&wdtthi, g_wdtt_hi);
    cudaGetSymbolAddress((void**)&wdttlo, g_wdtt_lo);

    cudaFuncSetAttribute(bf16split_gemm<128,false>, cudaFuncAttributeMaxDynamicSharedMemorySize, GT_SMEM_128);
    cudaFuncSetAttribute(bf16split_gemm<128,true >, cudaFuncAttributeMaxDynamicSharedMemorySize, GT_SMEM_128);
    cudaFuncSetAttribute(bf16split_gemm<64, false>, cudaFuncAttributeMaxDynamicSharedMemorySize, GT_SMEM_64);

    // 1: LayerNorm -> bf16 split h
    ln_kernel<<<ROWS, 256>>>(x, gamma, beta);

    // 2: W_in transpose+split
    transpose_split_kernel<<<dim3((2*D_INNER)/32, D_MODEL/32), dim3(32, 8)>>>(
        W_in, D_MODEL, 2*D_INNER, winthi, wintlo);

    // 3: xz = h @ W_in   (HMMA bf16-split, 2-stage)
    bf16split_gemm<128,false><<<dim3((2*D_INNER)/128, ROWS/128), 256, GT_SMEM_128>>>(
        hhi, hlo, winthi, wintlo, xz, nullptr, nullptr, ROWS, 2*D_INNER, D_MODEL);

    // 4: u = silu(depthwise_conv(xi) + b_conv)   <-- ncu capture slot
    conv_silu_kernel<<<dim3(D_INNER/512, SEQ/CONV_TSEG, BATCH), 128>>>(W_conv, b_conv);

    // 5: x_dbl = u @ W_x  (smem-staged)
    xdbl_kernel<<<ROWS/XDBL_RPB, 128>>>(W_x);

    // 6: W_dt transpose+split
    transpose_split_kernel<<<dim3(D_INNER/32, DT_RANK/32), dim3(32, 8)>>>(
        W_dt, DT_RANK, D_INNER, wdtthi, wdttlo);

    // 7: dt = softplus(dt_r @ W_dt + b_dt)   (HMMA bf16-split, 2-stage)
    bf16split_gemm<128,true><<<dim3(D_INNER/128, ROWS/128), 256, GT_SMEM_128>>>(
        dtrhi, dtrlo, wdtthi, wdttlo, dt, nullptr, b_dt, ROWS, D_INNER, DT_RANK);

    // 8: sequential scan + Dskip + silu(z) gate -> bf16 split y
    scan_kernel<<<BATCH * (D_INNER/32), 512>>>(A_log, Dskip);

    // 9: W_out transpose+split
    transpose_split_kernel<<<dim3(D_MODEL/32, D_INNER/32), dim3(32, 8)>>>(
        W_out, D_INNER, D_MODEL, wothi, wotlo);

    // 10: out = x + y @ W_out  (HMMA bf16-split, BM=64, 2-stage)
    bf16split_gemm<64,false><<<dim3(D_MODEL/128, ROWS/64), 256, GT_SMEM_64>>>(
        yhi, ylo, wothi, wotlo, out, x, nullptr, ROWS, D_MODEL, D_INNER);
}

// round 15
// speedup vs baseline: 1.0812x; 1.0091x over previous
#include <cuda_runtime.h>
#include <cuda_bf16.h>
#include <cstdint>
#include <math.h>

// Problem constants
#define D_MODEL  1024
#define D_INNER  2048
#define D_STATE  16
#define D_CONV   4
#define DT_RANK  64
#define BATCH    2
#define SEQ      1024
#define ROWS     (BATCH*SEQ)           // 2048
#define XDBL_W   (DT_RANK + 2*D_STATE) // 96

// ---------------------------------------------------------------------------
// Scratch (static device arrays; no allocation allowed)
// ---------------------------------------------------------------------------
__device__ float g_xz  [ROWS * 2 * D_INNER];    // [xi | z]
__device__ float g_u   [ROWS * D_INNER];
__device__ float g_xdbl[ROWS * XDBL_W];         // [dt_r | B | C] (B,C used by scan)
__device__ float g_dt  [ROWS * D_INNER];

// bf16 split operands for tensor-core GEMMs
__device__ __nv_bfloat16 g_hhi [ROWS * D_MODEL];
__device__ __nv_bfloat16 g_hlo [ROWS * D_MODEL];
__device__ __nv_bfloat16 g_wint_hi[(2*D_INNER) * D_MODEL]; // W_in^T  [4096,1024]
__device__ __nv_bfloat16 g_wint_lo[(2*D_INNER) * D_MODEL];
__device__ __nv_bfloat16 g_yhi [ROWS * D_INNER];
__device__ __nv_bfloat16 g_ylo [ROWS * D_INNER];
__device__ __nv_bfloat16 g_wot_hi[D_MODEL * D_INNER];      // W_out^T [1024,2048]
__device__ __nv_bfloat16 g_wot_lo[D_MODEL * D_INNER];
__device__ __nv_bfloat16 g_dtr_hi[ROWS * DT_RANK];         // dt_r split [2048,64]
__device__ __nv_bfloat16 g_dtr_lo[ROWS * DT_RANK];
__device__ __nv_bfloat16 g_wdtt_hi[D_INNER * DT_RANK];     // W_dt^T [2048,64]
__device__ __nv_bfloat16 g_wdtt_lo[D_INNER * DT_RANK];

// ---------------------------------------------------------------------------
// PTX helpers (sm_80-era only: ldmatrix / mma.sync / cp.async)
// ---------------------------------------------------------------------------
__device__ __forceinline__ uint32_t smem_to_u32(const void* p) {
    uint32_t a;
    asm("{ .reg .u64 t; cvta.to.shared.u64 t, %1; cvt.u32.u64 %0, t; }" : "=r"(a) : "l"(p));
    return a;
}
#define CP_ASYNC_16(dst_u32, src_ptr) \
    asm volatile("cp.async.cg.shared.global [%0], [%1], 16;" :: "r"(dst_u32), "l"(src_ptr))
#define CP_COMMIT() asm volatile("cp.async.commit_group;" ::: "memory")
#define CP_WAIT(n)  asm volatile("cp.async.wait_group %0;" :: "n"(n) : "memory")

#define LDSM_X4(r0,r1,r2,r3,addr) \
    asm volatile("ldmatrix.sync.aligned.m8n8.x4.shared.b16 {%0,%1,%2,%3}, [%4];" \
        : "=r"(r0),"=r"(r1),"=r"(r2),"=r"(r3) : "r"(addr))

__device__ __forceinline__ void mma_bf16(float* c, const uint32_t* a, const uint32_t* b) {
    asm volatile(
        "mma.sync.aligned.m16n8k16.row.col.f32.bf16.bf16.f32 "
        "{%0,%1,%2,%3}, {%4,%5,%6,%7}, {%8,%9}, {%0,%1,%2,%3};"
        : "+f"(c[0]), "+f"(c[1]), "+f"(c[2]), "+f"(c[3])
        : "r"(a[0]), "r"(a[1]), "r"(a[2]), "r"(a[3]), "r"(b[0]), "r"(b[1]));
}

// ---------------------------------------------------------------------------
// Math helpers
// ---------------------------------------------------------------------------
__device__ __forceinline__ float sigmoidf_(float x) { return 1.0f / (1.0f + __expf(-x)); }
__device__ __forceinline__ float softplusf_(float x) {
    return fmaxf(x, 0.0f) + log1pf(__expf(-fabsf(x)));
}
__device__ __forceinline__ void split_bf16(float v, __nv_bfloat16& hi, __nv_bfloat16& lo) {
    hi = __float2bfloat16(v);
    lo = __float2bfloat16(v - __bfloat162float(hi));
}

// ---------------------------------------------------------------------------
// K1: LayerNorm -> bf16-split (g_hhi / g_hlo)
// ---------------------------------------------------------------------------
__global__ void ln_kernel(const float* __restrict__ x,
                          const float* __restrict__ gamma,
                          const float* __restrict__ beta) {
    const int row = blockIdx.x;
    const int tid = threadIdx.x;
    const float4* xv = reinterpret_cast<const float4*>(x + (size_t)row * D_MODEL);
    float4 v = xv[tid];
    float s  = v.x + v.y + v.z + v.w;
    float s2 = v.x*v.x + v.y*v.y + v.z*v.z + v.w*v.w;

    #pragma unroll
    for (int o = 16; o > 0; o >>= 1) {
        s  += __shfl_xor_sync(0xffffffffu, s,  o);
        s2 += __shfl_xor_sync(0xffffffffu, s2, o);
    }
    __shared__ float red0[8], red1[8];
    const int wid = tid >> 5, lane = tid & 31;
    if (lane == 0) { red0[wid] = s; red1[wid] = s2; }
    __syncthreads();
    if (wid == 0) {
        s  = (lane < 8) ? red0[lane] : 0.f;
        s2 = (lane < 8) ? red1[lane] : 0.f;
        #pragma unroll
        for (int o = 4; o > 0; o >>= 1) {
            s  += __shfl_xor_sync(0xffffffffu, s,  o);
            s2 += __shfl_xor_sync(0xffffffffu, s2, o);
        }
        if (lane == 0) { red0[0] = s; red1[0] = s2; }
    }
    __syncthreads();
    const float mean = red0[0] * (1.0f / D_MODEL);
    const float var  = red1[0] * (1.0f / D_MODEL) - mean * mean;
    const float rstd = rsqrtf(var + 1e-5f);

    const float4 g  = reinterpret_cast<const float4*>(gamma)[tid];
    const float4 be = reinterpret_cast<const float4*>(beta)[tid];
    float o[4];
    o[0] = (v.x - mean) * rstd * g.x + be.x;
    o[1] = (v.y - mean) * rstd * g.y + be.y;
    o[2] = (v.z - mean) * rstd * g.z + be.z;
    o[3] = (v.w - mean) * rstd * g.w + be.w;
    const size_t base = (size_t)row * D_MODEL + tid * 4;
    #pragma unroll
    for (int j = 0; j < 4; j++) {
        __nv_bfloat16 hi, lo;
        split_bf16(o[j], hi, lo);
        g_hhi[base + j] = hi;
        g_hlo[base + j] = lo;
    }
}

// ---------------------------------------------------------------------------
// K2: tiled transpose + bf16-split: in[R,C] fp32 -> out[C,R] (hi,lo)
// ---------------------------------------------------------------------------
__global__ void transpose_split_kernel(const float* __restrict__ in, int R, int C,
                                       __nv_bfloat16* __restrict__ outhi,
                                       __nv_bfloat16* __restrict__ outlo) {
    __shared__ float tile[32][33];
    const int c0 = blockIdx.x * 32;
    const int r0 = blockIdx.y * 32;
    const int tx = threadIdx.x, ty = threadIdx.y;   // 32 x 8
    #pragma unroll
    for (int i = 0; i < 32; i += 8)
        tile[ty + i][tx] = in[(size_t)(r0 + ty + i) * C + c0 + tx];
    __syncthreads();
    #pragma unroll
    for (int i = 0; i < 32; i += 8) {
        float v = tile[tx][ty + i];
        __nv_bfloat16 hi, lo;
        split_bf16(v, hi, lo);
        size_t oidx = (size_t)(c0 + ty + i) * R + r0 + tx;
        outhi[oidx] = hi;
        outlo[oidx] = lo;
    }
}

// ---------------------------------------------------------------------------
// K3: bf16-split GEMM via mma.sync — 2-stage (80KB => 2 CTAs/SM; measured best)
//   C[M,N] = op(Ahi@B^T(3-term) [+bias][softplus]) [+ Cadd]
// ---------------------------------------------------------------------------
#define GT_ROWB    80

template<int BMROWS>
__device__ __forceinline__ void tile_cp_async(uint32_t smem_tile,
                                              const __nv_bfloat16* __restrict__ src,
                                              int ldk, int tid) {
    #pragma unroll
    for (int i = tid; i < BMROWS * 4; i += 256) {
        const int row   = i >> 2;
        const int chunk = i & 3;
        const __nv_bfloat16* g = src + (size_t)row * ldk + chunk * 8;
        CP_ASYNC_16(smem_tile + row * GT_ROWB + chunk * 16, g);
    }
}

template<int BM, bool SOFTPLUS>
__global__ void __launch_bounds__(256)
bf16split_gemm(const __nv_bfloat16* __restrict__ Ahi, const __nv_bfloat16* __restrict__ Alo,
               const __nv_bfloat16* __restrict__ Bhi, const __nv_bfloat16* __restrict__ Blo,
               float* __restrict__ C, const float* __restrict__ Cadd,
               const float* __restrict__ bias,
               int M, int N, int K) {
    constexpr int MI      = BM / 32;                 // m-fragments per warp
    constexpr int A_TILE  = BM * GT_ROWB;
    constexpr int B_TILE  = 128 * GT_ROWB;
    constexpr int ST_AHI  = 0;
    constexpr int ST_ALO  = ST_AHI + A_TILE;
    constexpr int ST_BHI  = ST_ALO + A_TILE;
    constexpr int ST_BLO  = ST_BHI + B_TILE;
    constexpr int STAGE   = 2 * A_TILE + 2 * B_TILE;

    extern __shared__ char smem[];
    const uint32_t sbase = smem_to_u32(smem);
    const int tid = threadIdx.x;
    const int wid = tid >> 5, L = tid & 31;
    const int wm = wid & 1;
    const int wn = wid >> 1;
    const int m0 = blockIdx.y * BM;
    const int n0 = blockIdx.x * 128;

    const uint32_t a_lane = (uint32_t)((wm * (BM / 2) + (L & 15)) * GT_ROWB + (L >> 4) * 16);
    const uint32_t b_lane = (uint32_t)((wn * 32 + (L & 7) + ((L >> 4) << 3)) * GT_ROWB
                                       + ((L >> 3) & 1) * 16);

    float acc[MI][4][4];
    #pragma unroll
    for (int i = 0; i < MI; i++)
        #pragma unroll
        for (int j = 0; j < 4; j++)
            #pragma unroll
            for (int k = 0; k < 4; k++) acc[i][j][k] = 0.f;

    const int NC = K >> 5;
    const size_t abase = (size_t)m0 * K;
    const size_t bbase = (size_t)n0 * K;

    {
        tile_cp_async<BM >(sbase + ST_AHI, Ahi + abase, K, tid);
        tile_cp_async<BM >(sbase + ST_ALO, Alo + abase, K, tid);
        tile_cp_async<128>(sbase + ST_BHI, Bhi + bbase, K, tid);
        tile_cp_async<128>(sbase + ST_BLO, Blo + bbase, K, tid);
        CP_COMMIT();
    }

    for (int c = 0; c < NC; c++) {
        const uint32_t stage = sbase + (c & 1) * STAGE;

        if (c + 1 < NC) {
            const uint32_t nstage = sbase + ((c + 1) & 1) * STAGE;
            const int kc = (c + 1) << 5;
            tile_cp_async<BM >(nstage + ST_AHI, Ahi + abase + kc, K, tid);
            tile_cp_async<BM >(nstage + ST_ALO, Alo + abase + kc, K, tid);
            tile_cp_async<128>(nstage + ST_BHI, Bhi + bbase + kc, K, tid);
            tile_cp_async<128>(nstage + ST_BLO, Blo + bbase + kc, K, tid);
            CP_COMMIT();
            CP_WAIT(1);
        } else {
            CP_WAIT(0);
        }
        __syncthreads();

        const uint32_t sAhi = stage + ST_AHI + a_lane;
        const uint32_t sAlo = stage + ST_ALO + a_lane;
        const uint32_t sBhi = stage + ST_BHI + b_lane;
        const uint32_t sBlo = stage + ST_BLO + b_lane;

        #pragma unroll
        for (int ks = 0; ks < 2; ks++) {
            uint32_t bh[8], bl[8];
            LDSM_X4(bh[0], bh[1], bh[2], bh[3], sBhi + 0 * 16 * GT_ROWB + ks * 32);
            LDSM_X4(bh[4], bh[5], bh[6], bh[7], sBhi + 1 * 16 * GT_ROWB + ks * 32);
            LDSM_X4(bl[0], bl[1], bl[2], bl[3], sBlo + 0 * 16 * GT_ROWB + ks * 32);
            LDSM_X4(bl[4], bl[5], bl[6], bl[7], sBlo + 1 * 16 * GT_ROWB + ks * 32);
            #pragma unroll
            for (int mi = 0; mi < MI; mi++) {
                uint32_t ah[4], al[4];
                LDSM_X4(ah[0], ah[1], ah[2], ah[3], sAhi + mi * 16 * GT_ROWB + ks * 32);
                LDSM_X4(al[0], al[1], al[2], al[3], sAlo + mi * 16 * GT_ROWB + ks * 32);
                #pragma unroll
                for (int ni = 0; ni < 4; ni++) {
                    mma_bf16(acc[mi][ni], ah, &bh[ni * 2]);
                    mma_bf16(acc[mi][ni], ah, &bl[ni * 2]);
                    mma_bf16(acc[mi][ni], al, &bh[ni * 2]);
                }
            }
        }
        __syncthreads();
    }

    const int g  = L >> 2;
    const int tg = L & 3;
    #pragma unroll
    for (int mi = 0; mi < MI; mi++) {
        const int r0 = m0 + wm * (BM / 2) + mi * 16 + g;
        #pragma unroll
        for (int ni = 0; ni < 4; ni++) {
            const int cc = n0 + wn * 32 + ni * 8 + tg * 2;
            float2 v0 = make_float2(acc[mi][ni][0], acc[mi][ni][1]);
            float2 v1 = make_float2(acc[mi][ni][2], acc[mi][ni][3]);
            if (bias) {
                const float2 bv = *reinterpret_cast<const float2*>(bias + cc);
                v0.x += bv.x; v0.y += bv.y;
                v1.x += bv.x; v1.y += bv.y;
            }
            if (SOFTPLUS) {
                v0.x = softplusf_(v0.x); v0.y = softplusf_(v0.y);
                v1.x = softplusf_(v1.x); v1.y = softplusf_(v1.y);
            }
            if (Cadd) {
                const float2 a0 = *reinterpret_cast<const float2*>(Cadd + (size_t)r0 * N + cc);
                const float2 a1 = *reinterpret_cast<const float2*>(Cadd + (size_t)(r0 + 8) * N + cc);
                v0.x += a0.x; v0.y += a0.y;
                v1.x += a1.x; v1.y += a1.y;
            }
            *reinterpret_cast<float2*>(C + (size_t)r0 * N + cc)       = v0;
            *reinterpret_cast<float2*>(C + (size_t)(r0 + 8) * N + cc) = v1;
        }
    }
}

#define GT_SMEM_128  (2 * (2 * 128 * GT_ROWB + 2 * 128 * GT_ROWB))   // 81920
#define GT_SMEM_64   (2 * (2 * 64  * GT_ROWB + 2 * 128 * GT_ROWB))   // 61440

// ---------------------------------------------------------------------------
// K4: depthwise causal conv + bias + silu — float4 lanes AND 512 CTAs.
// ---------------------------------------------------------------------------
#define CONV_TSEG 16
__global__ void __launch_bounds__(128) conv_silu_kernel(const float* __restrict__ Wc,
                                                        const float* __restrict__ bc) {
    const int d4 = (blockIdx.x * 128 + threadIdx.x) * 4;   // 4 consecutive d
    const int t0 = blockIdx.y * CONV_TSEG;
    const int b  = blockIdx.z;
    const int rowbase = b * SEQ + t0;

    float4 W[4];
    #pragma unroll
    for (int j = 0; j < 4; j++)
        W[j] = *reinterpret_cast<const float4*>(Wc + (size_t)(d4 + j) * D_CONV);
    const float4 bias = *reinterpret_cast<const float4*>(bc + d4);

    float4 xm3 = (t0 >= 3) ? *reinterpret_cast<const float4*>(g_xz + (size_t)(rowbase - 3) * (2 * D_INNER) + d4)
                           : make_float4(0.f, 0.f, 0.f, 0.f);
    float4 xm2 = (t0 >= 2) ? *reinterpret_cast<const float4*>(g_xz + (size_t)(rowbase - 2) * (2 * D_INNER) + d4)
                           : make_float4(0.f, 0.f, 0.f, 0.f);
    float4 xm1 = (t0 >= 1) ? *reinterpret_cast<const float4*>(g_xz + (size_t)(rowbase - 1) * (2 * D_INNER) + d4)
                           : make_float4(0.f, 0.f, 0.f, 0.f);

    #pragma unroll
    for (int t = 0; t < CONV_TSEG; t++) {
        const float4 x0 = *reinterpret_cast<const float4*>(
            g_xz + (size_t)(rowbase + t) * (2 * D_INNER) + d4);
        float4 o;
        {
            float a0 = bias.x;
            a0 = fmaf(xm3.x, W[0].x, a0); a0 = fmaf(xm2.x, W[0].y, a0);
            a0 = fmaf(xm1.x, W[0].z, a0); a0 = fmaf(x0.x,  W[0].w, a0);
            o.x = a0 * sigmoidf_(a0);
            float a1 = bias.y;
            a1 = fmaf(xm3.y, W[1].x, a1); a1 = fmaf(xm2.y, W[1].y, a1);
            a1 = fmaf(xm1.y, W[1].z, a1); a1 = fmaf(x0.y,  W[1].w, a1);
            o.y = a1 * sigmoidf_(a1);
            float a2 = bias.z;
            a2 = fmaf(xm3.z, W[2].x, a2); a2 = fmaf(xm2.z, W[2].y, a2);
            a2 = fmaf(xm1.z, W[2].z, a2); a2 = fmaf(x0.z,  W[2].w, a2);
            o.z = a2 * sigmoidf_(a2);
            float a3 = bias.w;
            a3 = fmaf(xm3.w, W[3].x, a3); a3 = fmaf(xm2.w, W[3].y, a3);
            a3 = fmaf(xm1.w, W[3].z, a3); a3 = fmaf(x0.w,  W[3].w, a3);
            o.w = a3 * sigmoidf_(a3);
        }
        *reinterpret_cast<float4*>(g_u + (size_t)(rowbase + t) * D_INNER + d4) = o;
        xm3 = xm2; xm2 = xm1; xm1 = x0;
    }
}

// ---------------------------------------------------------------------------
// K5: x_dbl = u @ W_x  [2048,2048]x[2048,96] — smem-staged Wx + transposed u.
// ---------------------------------------------------------------------------
#define XDBL_RPB 8
#define XDBL_KC  64
#define XDBL_UP  12
__global__ void __launch_bounds__(128) xdbl_kernel(const float* __restrict__ Wx) {
    __shared__ __align__(16) float ws[XDBL_KC * XDBL_W];     // 24 KB
    __shared__ __align__(16) float us[XDBL_KC * XDBL_UP];    //  3 KB
    const int tid = threadIdx.x;
    const int row0 = blockIdx.x * XDBL_RPB;

    float acc[XDBL_RPB];
    #pragma unroll
    for (int r = 0; r < XDBL_RPB; r++) acc[r] = 0.f;

    const int ur = tid >> 4;
    const int uk = (tid & 15) * 4;

    for (int k0 = 0; k0 < D_INNER; k0 += XDBL_KC) {
        __syncthreads();
        const float4* wsrc = reinterpret_cast<const float4*>(Wx + (size_t)k0 * XDBL_W);
        #pragma unroll
        for (int i = tid; i < (XDBL_KC * XDBL_W) / 4; i += 128)
            reinterpret_cast<float4*>(ws)[i] = wsrc[i];
        {
            float4 v = *reinterpret_cast<const float4*>(
                g_u + (size_t)(row0 + ur) * D_INNER + k0 + uk);
            us[(uk + 0) * XDBL_UP + ur] = v.x;
            us[(uk + 1) * XDBL_UP + ur] = v.y;
            us[(uk + 2) * XDBL_UP + ur] = v.z;
            us[(uk + 3) * XDBL_UP + ur] = v.w;
        }
        __syncthreads();
        if (tid < XDBL_W) {
            #pragma unroll 8
            for (int k = 0; k < XDBL_KC; k++) {
                const float w  = ws[k * XDBL_W + tid];
                const float4 ua = *reinterpret_cast<const float4*>(&us[k * XDBL_UP + 0]);
                const float4 ub = *reinterpret_cast<const float4*>(&us[k * XDBL_UP + 4]);
                acc[0] = fmaf(ua.x, w, acc[0]);
                acc[1] = fmaf(ua.y, w, acc[1]);
                acc[2] = fmaf(ua.z, w, acc[2]);
                acc[3] = fmaf(ua.w, w, acc[3]);
                acc[4] = fmaf(ub.x, w, acc[4]);
                acc[5] = fmaf(ub.y, w, acc[5]);
                acc[6] = fmaf(ub.z, w, acc[6]);
                acc[7] = fmaf(ub.w, w, acc[7]);
            }
        }
    }
    if (tid < DT_RANK) {
        #pragma unroll
        for (int r = 0; r < XDBL_RPB; r++) {
            __nv_bfloat16 hi, lo;
            split_bf16(acc[r], hi, lo);
            g_dtr_hi[(size_t)(row0 + r) * DT_RANK + tid] = hi;
            g_dtr_lo[(size_t)(row0 + r) * DT_RANK + tid] = lo;
        }
    } else if (tid < XDBL_W) {
        #pragma unroll
        for (int r = 0; r < XDBL_RPB; r++)
            g_xdbl[(size_t)(row0 + r) * XDBL_W + tid] = acc[r];
    }
}

// ---------------------------------------------------------------------------
// K7: SSM scan — 16-d tiles => 256 blocks x 256 threads, 32-step chunks,
//     double-buffered cp.async staging.  thread = (dloc = (tid>>4)&15, n = tid&15)
// ---------------------------------------------------------------------------
#define SC_TC 32
#define SC_D  16
struct ScanSmem {
    float dt[2][SC_TC][SC_D];
    float u [2][SC_TC][SC_D];
    float z [2][SC_TC][SC_D];
    float B [2][SC_TC][16];
    float C [2][SC_TC][16];
    float y [SC_TC][SC_D];
};

__device__ __forceinline__ void scan_prefetch(ScanSmem* ss, uint32_t sb, int buf,
                                              int rowbase, int t0, int d0, int tid) {
    const uint32_t dt_b = sb + (uint32_t)((char*)&ss->dt[buf][0][0] - (char*)ss);
    const uint32_t u_b  = sb + (uint32_t)((char*)&ss->u [buf][0][0] - (char*)ss);
    const uint32_t z_b  = sb + (uint32_t)((char*)&ss->z [buf][0][0] - (char*)ss);
    const uint32_t B_b  = sb + (uint32_t)((char*)&ss->B [buf][0][0] - (char*)ss);
    const uint32_t C_b  = sb + (uint32_t)((char*)&ss->C [buf][0][0] - (char*)ss);

    // 640 cp.async.16 total: dt 128 | u 128 | z 128 | B 128 | C 128
    #pragma unroll
    for (int i = tid; i < 640; i += 256) {
        const int seg = i >> 7;          // 0..4
        const int j   = i & 127;
        const int r   = j >> 2;          // timestep 0..31
        const int cq  = (j & 3) * 4;     // quad offset (floats)
        const int row = rowbase + t0 + r;
        if (seg == 0) {
            CP_ASYNC_16(dt_b + (r * SC_D + cq) * 4,
                        g_dt + (size_t)row * D_INNER + d0 + cq);
        } else if (seg == 1) {
            CP_ASYNC_16(u_b + (r * SC_D + cq) * 4,
                        g_u + (size_t)row * D_INNER + d0 + cq);
        } else if (seg == 2) {
            CP_ASYNC_16(z_b + (r * SC_D + cq) * 4,
                        g_xz + (size_t)row * (2 * D_INNER) + D_INNER + d0 + cq);
        } else if (seg == 3) {
            CP_ASYNC_16(B_b + (r * 16 + cq) * 4,
                        g_xdbl + (size_t)row * XDBL_W + DT_RANK + cq);
        } else {
            CP_ASYNC_16(C_b + (r * 16 + cq) * 4,
                        g_xdbl + (size_t)row * XDBL_W + DT_RANK + D_STATE + cq);
        }
    }
}

__global__ void __launch_bounds__(256) scan_kernel(const float* __restrict__ A_log,
                                                   const float* __restrict__ Dskip) {
    __shared__ ScanSmem ss;
    const uint32_t sb = smem_to_u32(&ss);
    const int tid  = threadIdx.x;
    const int n    = tid & 15;
    const int dloc = (tid >> 4) & 15;        // 0..15
    const int b    = blockIdx.x >> 7;        // /128
    const int dblk = blockIdx.x & 127;
    const int d0   = dblk * SC_D;
    const int d    = d0 + dloc;
    const int rowbase = b * SEQ;

    const float a   = -__expf(A_log[d * D_STATE + n]);
    const float dsk = Dskip[d];

    float hstate = 0.f;

    scan_prefetch(&ss, sb, 0, rowbase, 0, d0, tid);
    CP_COMMIT();

    const int NCH = SEQ / SC_TC;   // 32
    for (int c = 0; c < NCH; c++) {
        const int buf = c & 1;
        if (c + 1 < NCH) {
            scan_prefetch(&ss, sb, buf ^ 1, rowbase, (c + 1) * SC_TC, d0, tid);
            CP_COMMIT();
            CP_WAIT(1);
        } else {
            CP_WAIT(0);
        }
        __syncthreads();

        #pragma unroll
        for (int i = 0; i < SC_TC; i++) {
            const float dtv = ss.dt[buf][i][dloc];
            const float uv  = ss.u [buf][i][dloc];
            const float Bv  = ss.B [buf][i][n];
            const float Cv  = ss.C [buf][i][n];

            const float dA = __expf(dtv * a);
            hstate = fmaf(dA, hstate, (dtv * uv) * Bv);
            float p = hstate * Cv;
            p += __shfl_xor_sync(0xffffffffu, p, 1);
            p += __shfl_xor_sync(0xffffffffu, p, 2);
            p += __shfl_xor_sync(0xffffffffu, p, 4);
            p += __shfl_xor_sync(0xffffffffu, p, 8);
            if (n == 0) {
                const float zv = ss.z[buf][i][dloc];
                ss.y[i][dloc] = (p + uv * dsk) * (zv * sigmoidf_(zv));
            }
        }
        __syncthreads();

        // writeout: 512 y values over 256 threads (2 each)
        #pragma unroll
        for (int j = 0; j < 2; j++) {
            const int it = (tid >> 4) + j * 16;
            const int dd = tid & 15;
            const float yv = ss.y[it][dd];
            __nv_bfloat16 hi, lo;
            split_bf16(yv, hi, lo);
            const size_t idx = (size_t)(rowbase + c * SC_TC + it) * D_INNER + d0 + dd;
            g_yhi[idx] = hi;
            g_ylo[idx] = lo;
        }
    }
}

// ---------------------------------------------------------------------------
// Launch  (4th launch = conv_silu_kernel for ncu instrumentation / control)
// ---------------------------------------------------------------------------
extern "C" void kernel_launch(void* const* d_in, const int* in_sizes, int n_in,
                              void* d_out, int out_size) {
    const float* x      = (const float*)d_in[0];
    const float* gamma  = (const float*)d_in[1];
    const float* beta   = (const float*)d_in[2];
    const float* W_in   = (const float*)d_in[3];
    const float* W_conv = (const float*)d_in[4];
    const float* b_conv = (const float*)d_in[5];
    const float* W_x    = (const float*)d_in[6];
    const float* W_dt   = (const float*)d_in[7];
    const float* b_dt   = (const float*)d_in[8];
    const float* A_log  = (const float*)d_in[9];
    const float* Dskip  = (const float*)d_in[10];
    const float* W_out  = (const float*)d_in[11];
    float* out = (float*)d_out;

    float *xz, *u, *xdbl, *dt;
    cudaGetSymbolAddress((void**)&xz,   g_xz);
    cudaGetSymbolAddress((void**)&u,    g_u);
    cudaGetSymbolAddress((void**)&xdbl, g_xdbl);
    cudaGetSymbolAddress((void**)&dt,   g_dt);
    __nv_bfloat16 *hhi, *hlo, *winthi, *wintlo, *yhi, *ylo, *wothi, *wotlo;
    __nv_bfloat16 *dtrhi, *dtrlo, *wdtthi, *wdttlo;
    cudaGetSymbolAddress((void**)&hhi,    g_hhi);
    cudaGetSymbolAddress((void**)&hlo,    g_hlo);
    cudaGetSymbolAddress((void**)&winthi, g_wint_hi);
    cudaGetSymbolAddress((void**)&wintlo, g_wint_lo);
    cudaGetSymbolAddress((void**)&yhi,    g_yhi);
    cudaGetSymbolAddress((void**)&ylo,    g_ylo);
    cudaGetSymbolAddress((void**)&wothi,  g_wot_hi);
    cudaGetSymbolAddress((void**)&wotlo,  g_wot_lo);
    cudaGetSymbolAddress((void**)&dtrhi,  g_dtr_hi);
    cudaGetSymbolAddress((void**)&dtrlo,  g_dtr_lo);
    cudaGetSymbolAddress((void**)&wdtthi, g_wdtt_hi);
    cudaGetSymbolAddress((void**)&wdttlo, g_wdtt_lo);

    cudaFuncSetAttribute(bf16split_gemm<128,false>, cudaFuncAttributeMaxDynamicSharedMemorySize, GT_SMEM_128);
    cudaFuncSetAttribute(bf16split_gemm<128,true >, cudaFuncAttributeMaxDynamicSharedMemorySize, GT_SMEM_128);
    cudaFuncSetAttribute(bf16split_gemm<64, false>, cudaFuncAttributeMaxDynamicSharedMemorySize, GT_SMEM_64);

    // 1: LayerNorm -> bf16 split h
    ln_kernel<<<ROWS, 256>>>(x, gamma, beta);

    // 2: W_in transpose+split
    transpose_split_kernel<<<dim3((2*D_INNER)/32, D_MODEL/32), dim3(32, 8)>>>(
        W_in, D_MODEL, 2*D_INNER, winthi, wintlo);

    // 3: xz = h @ W_in   (HMMA bf16-split, 2-stage)
    bf16split_gemm<128,false><<<dim3((2*D_INNER)/128, ROWS/128), 256, GT_SMEM_128>>>(
        hhi, hlo, winthi, wintlo, xz, nullptr, nullptr, ROWS, 2*D_INNER, D_MODEL);

    // 4: u = silu(depthwise_conv(xi) + b_conv)   <-- ncu capture slot (control)
    conv_silu_kernel<<<dim3(D_INNER/512, SEQ/CONV_TSEG, BATCH), 128>>>(W_conv, b_conv);

    // 5: x_dbl = u @ W_x  (smem-staged)
    xdbl_kernel<<<ROWS/XDBL_RPB, 128>>>(W_x);

    // 6: W_dt transpose+split
    transpose_split_kernel<<<dim3(D_INNER/32, DT_RANK/32), dim3(32, 8)>>>(
        W_dt, DT_RANK, D_INNER, wdtthi, wdttlo);

    // 7: dt = softplus(dt_r @ W_dt + b_dt)   (HMMA bf16-split, 2-stage)
    bf16split_gemm<128,true><<<dim3(D_INNER/128, ROWS/128), 256, GT_SMEM_128>>>(
        dtrhi, dtrlo, wdtthi, wdttlo, dt, nullptr, b_dt, ROWS, D_INNER, DT_RANK);

    // 8: sequential scan + Dskip + silu(z) gate -> bf16 split y  (256 blocks)
    scan_kernel<<<BATCH * (D_INNER/SC_D), 256>>>(A_log, Dskip);

    // 9: W_out transpose+split
    transpose_split_kernel<<<dim3(D_MODEL/32, D_INNER/32), dim3(32, 8)>>>(
        W_out, D_INNER, D_MODEL, wothi, wotlo);

    // 10: out = x + y @ W_out  (HMMA bf16-split, BM=64, 2-stage)
    bf16split_gemm<64,false><<<dim3(D_MODEL/128, ROWS/64), 256, GT_SMEM_64>>>(
        yhi, ylo, wothi, wotlo, out, x, nullptr, ROWS, D_MODEL, D_INNER);
}